// round 8
// baseline (speedup 1.0000x reference)
#include <cuda_runtime.h>
#include <cstdint>

// Problem constants (from reference): B=32, S=1024, D=512
#define BB 32
#define SS 1024
#define DD 512
#define DV4 (DD / 4)        // 128 float4 per row
#define CHUNK 8             // source rows per block
#define NBLK (SS / CHUNK)   // 128 s-blocks per batch
#define NTAILB 16           // last s-blocks per batch sharing tail zero-fill

// ---------------------------------------------------------------------------
// Single fused kernel: per-block redundant prefix (durations row is L2-hot),
// scatter-expand of CHUNK source rows, fused tail zero-fill, lengths output.
// Grid: (NBLK, BB) = 4096 blocks of 128 threads -> single wave on 148 SMs.
// ---------------------------------------------------------------------------
__global__ void __launch_bounds__(128)
lenreg_kernel(const float4* __restrict__ x4,
              const float*  __restrict__ dur,
              const int*    __restrict__ scale_raw,
              float4* __restrict__ out4, int T,
              float* __restrict__ len_out, int write_len)
{
    const int b    = blockIdx.y;
    const int s0   = blockIdx.x * CHUNK;
    const int tid  = threadIdx.x;
    const int lane = tid & 31;
    const int warp = tid >> 5;

    // duration_scale dtype is ambiguous (python int 1 vs float 1.0).
    // Interpret the raw word as float if in a sane range, else as int.
    const int   iv = scale_raw[0];
    const float fv = __int_as_float(iv);
    const float af = fabsf(fv);
    const float scale = (af >= 1e-6f && af <= 1e6f) ? fv : (float)iv;

    // ---- redundant per-block prefix: sum d over [0, s0) and total over [0,S)
    const float* db = dur + b * SS;
    int sum_lt = 0, sum_all = 0;
    #pragma unroll
    for (int k = 0; k < SS / 128; ++k) {
        const int e = tid + k * 128;
        const float dvf = __ldg(&db[e]);
        int d = (int)(dvf * scale + 0.5f);   // trunc == astype(int32) for nonneg
        if (d < 1) d = 1;
        sum_all += d;
        if (e < s0) sum_lt += d;
    }
    sum_lt  = __reduce_add_sync(0xffffffffu, sum_lt);
    sum_all = __reduce_add_sync(0xffffffffu, sum_all);
    __shared__ int s_lt[4], s_all[4];
    if (lane == 0) { s_lt[warp] = sum_lt; s_all[warp] = sum_all; }
    __syncthreads();
    const int start0 = s_lt[0] + s_lt[1] + s_lt[2] + s_lt[3];
    const int tot    = s_all[0] + s_all[1] + s_all[2] + s_all[3];

    // ---- local durations for this block's CHUNK rows (uniform loads, L1-hot)
    int dloc[CHUNK];
    #pragma unroll
    for (int i = 0; i < CHUNK; ++i) {
        const float dvf = db[s0 + i];
        int d = (int)(dvf * scale + 0.5f);
        if (d < 1) d = 1;
        dloc[i] = d;
    }

    // ---- scatter-expand: read each x row once, stream d copies to output.
    // Software-pipelined: preload next row while storing current.
    const float4* xr = x4 + ((size_t)b * SS + s0) * DV4 + tid;
    float4 v = __ldcs(xr);
    int start = start0;
    #pragma unroll
    for (int i = 0; i < CHUNK; ++i) {
        float4 vn;
        if (i < CHUNK - 1) vn = __ldcs(xr + (i + 1) * DV4);
        const int d = dloc[i];
        float4* dst = out4 + ((size_t)b * T + start) * DV4 + tid;
        for (int r = 0; r < d; ++r) {
            __stcs(dst, v);
            dst += DV4;
        }
        start += d;
        v = vn;
    }

    // ---- fused tail zero-fill: rows [tot, T) shared by last NTAILB s-blocks
    if (blockIdx.x >= NBLK - NTAILB) {
        const int idx = blockIdx.x - (NBLK - NTAILB);
        const float4 z = make_float4(0.f, 0.f, 0.f, 0.f);
        for (int r = tot + idx; r < T; r += NTAILB) {
            __stcs(out4 + ((size_t)b * T + r) * DV4 + tid, z);
        }
    }

    // ---- total_lengths (as float) if the out buffer carries them
    if (write_len && blockIdx.x == NBLK - 1 && tid == 0)
        len_out[b] = (float)tot;
}

// ---------------------------------------------------------------------------
extern "C" void kernel_launch(void* const* d_in, const int* in_sizes, int n_in,
                              void* d_out, int out_size)
{
    const float4* x4    = (const float4*)d_in[0];   // x: (B,S,D) float32
    const float*  dur   = (const float*)d_in[1];    // durations: (B,S) float32
    const int*    scale = (const int*)d_in[2];      // duration_scale: scalar
    float* out = (float*)d_out;

    // Recover T (max total length) from out_size:
    //   out only:           out_size = B*T*D
    //   out + lengths tail: out_size = B*T*D + B
    int T, has_len;
    if (out_size % (BB * DD) == 0) {
        T = out_size / (BB * DD);
        has_len = 0;
    } else {
        T = (out_size - BB) / (BB * DD);
        has_len = 1;
    }

    lenreg_kernel<<<dim3(NBLK, BB), 128>>>(x4, dur, scale, (float4*)out, T,
                                           out + (size_t)BB * T * DD, has_len);
}

// round 9
// speedup vs baseline: 1.0326x; 1.0326x over previous
#include <cuda_runtime.h>
#include <cstdint>

// Problem constants (from reference): B=32, S=1024, D=512
#define BB 32
#define SS 1024
#define DD 512
#define DV4 (DD / 4)   // 128 float4 per row
#define TAILW 64       // s-blocks per batch sharing the tail zero-fill

// Scratch (allocation-free per harness rules)
__device__ int g_ends[BB * SS];   // inclusive cumsum of clamped durations, per batch
__device__ int g_totals[BB];      // total_lengths per batch

// ---------------------------------------------------------------------------
// Kernel A: per-batch duration round/clamp + inclusive scan.
// One block per batch, 256 threads, 4 durations/thread via float4.
// Triggers programmatic launch of the scatter kernel immediately at entry.
// ---------------------------------------------------------------------------
__global__ void __launch_bounds__(256)
durscan_kernel(const float* __restrict__ durations, const int* __restrict__ scale_raw,
               float* __restrict__ len_out, int write_len)
{
    cudaTriggerProgrammaticLaunchCompletion();   // let scatter start its prelude

    const int b   = blockIdx.x;
    const int tid = threadIdx.x;
    const int lane = tid & 31;
    const int warp = tid >> 5;

    // duration_scale dtype is ambiguous (python int 1 vs float 1.0).
    const int   iv = scale_raw[0];
    const float fv = __int_as_float(iv);
    const float af = fabsf(fv);
    const float scale = (af >= 1e-6f && af <= 1e6f) ? fv : (float)iv;

    // 4 consecutive durations per thread
    const float4 dv = __ldg(((const float4*)(durations + b * SS)) + tid);
    int d0 = (int)(dv.x * scale + 0.5f); if (d0 < 1) d0 = 1;
    int d1 = (int)(dv.y * scale + 0.5f); if (d1 < 1) d1 = 1;
    int d2 = (int)(dv.z * scale + 0.5f); if (d2 < 1) d2 = 1;
    int d3 = (int)(dv.w * scale + 0.5f); if (d3 < 1) d3 = 1;
    const int tsum = d0 + d1 + d2 + d3;

    // Inclusive scan of per-thread sums: warp shuffle + 8 warp partials.
    int v = tsum;
    #pragma unroll
    for (int o = 1; o < 32; o <<= 1) {
        int n = __shfl_up_sync(0xffffffffu, v, o);
        if (lane >= o) v += n;
    }
    __shared__ int wsum[8];
    if (lane == 31) wsum[warp] = v;
    __syncthreads();
    int wbase = 0, tot = 0;
    #pragma unroll
    for (int w = 0; w < 8; ++w) {
        if (w < warp) wbase += wsum[w];
        tot += wsum[w];
    }
    const int base = wbase + v - tsum;   // exclusive prefix for this thread

    int4 e;
    e.x = base + d0;
    e.y = e.x + d1;
    e.z = e.y + d2;
    e.w = e.z + d3;
    ((int4*)(g_ends + b * SS))[tid] = e;

    if (tid == 255) {
        g_totals[b] = tot;
        if (write_len) len_out[b] = (float)tot;
    }
}

// ---------------------------------------------------------------------------
// Kernel B: scatter-expand + fused tail zero-fill (PDL secondary).
// One 128-thread block per (s, b) source row. Loads its x row (independent of
// the scan) BEFORE the grid-dependency sync, then reads ends and streams
// d copies to the output.
// ---------------------------------------------------------------------------
__global__ void __launch_bounds__(128)
scatter_kernel(const float4* __restrict__ x4, float4* __restrict__ out4, int T)
{
    const int s = blockIdx.x;
    const int b = blockIdx.y;

    // Scan-independent prelude: start the x read stream early.
    const float4 v = __ldcs(&x4[((size_t)b * SS + s) * DV4 + threadIdx.x]);

    cudaGridDependencySynchronize();   // wait for durscan results

    const int end   = g_ends[b * SS + s];
    const int start = (s > 0) ? g_ends[b * SS + s - 1] : 0;

    float4* dst = out4 + ((size_t)b * T + start) * DV4 + threadIdx.x;
    for (int r = start; r < end; ++r) {
        __stcs(dst, v);
        dst += DV4;
    }

    // Fused tail zero-fill: rows [tot, T) shared across the last TAILW blocks.
    if (s >= SS - TAILW) {
        const int tot = g_totals[b];
        const float4 z = make_float4(0.f, 0.f, 0.f, 0.f);
        for (int r = tot + (s - (SS - TAILW)); r < T; r += TAILW) {
            __stcs(out4 + ((size_t)b * T + r) * DV4 + threadIdx.x, z);
        }
    }
}

// ---------------------------------------------------------------------------
extern "C" void kernel_launch(void* const* d_in, const int* in_sizes, int n_in,
                              void* d_out, int out_size)
{
    const float4* x4    = (const float4*)d_in[0];   // x: (B,S,D) float32
    const float*  dur   = (const float*)d_in[1];    // durations: (B,S) float32
    const int*    scale = (const int*)d_in[2];      // duration_scale: scalar
    float* out = (float*)d_out;

    // Recover T (max total length) from out_size:
    //   out only:           out_size = B*T*D
    //   out + lengths tail: out_size = B*T*D + B
    int T, has_len;
    if (out_size % (BB * DD) == 0) {
        T = out_size / (BB * DD);
        has_len = 0;
    } else {
        T = (out_size - BB) / (BB * DD);
        has_len = 1;
    }

    durscan_kernel<<<BB, 256>>>(dur, scale, out + (size_t)BB * T * DD, has_len);

    // Scatter as a programmatic dependent launch: overlaps its x-load prelude
    // with durscan's execution.
    cudaLaunchConfig_t cfg = {};
    cfg.gridDim  = dim3(SS, BB);
    cfg.blockDim = dim3(128);
    cfg.stream   = 0;
    cudaLaunchAttribute attr;
    attr.id = cudaLaunchAttributeProgrammaticStreamSerialization;
    attr.val.programmaticStreamSerializationAllowed = 1;
    cfg.attrs    = &attr;
    cfg.numAttrs = 1;
    float4* o4 = (float4*)out;
    cudaLaunchKernelEx(&cfg, scatter_kernel, x4, o4, T);
}